// round 1
// baseline (speedup 1.0000x reference)
#include <cuda_runtime.h>
#include <math.h>

#define T 2048
#define B 64
#define H 512
#define D 256
#define G_BLOCKS 96
#define NITER (T + 2)

// ---- scratch (static __device__ arrays: no allocation allowed) ----
__device__ float g_xT[(size_t)T * D * B];     // x transposed: [t][d][b]      (128 MB)
__device__ float g_xw0T[(size_t)T * H * B];   // layer0 input proj: [t][h][b] (256 MB)
__device__ float g_h1T[2][H * B];             // [parity][h][b]
__device__ float g_h2T[2][H * B];
__device__ float g_zT[2][H * B];              // W_ih1 @ h1 pre-activation
__device__ unsigned g_bar_count = 0;
__device__ volatile unsigned g_bar_phase = 0;

// ---- zero the recurrent state buffers (must happen every launch) ----
__global__ void k_zero() {
    int idx = blockIdx.x * 256 + threadIdx.x;
    if (idx < 2 * H * B) {
        ((float*)g_h1T)[idx] = 0.0f;
        ((float*)g_h2T)[idx] = 0.0f;
    }
}

// ---- transpose x[b][t][d] -> g_xT[t][d][b] (coalesced stores, L1 absorbs read amp) ----
__global__ void k_transpose(const float* __restrict__ x) {
    size_t n = (size_t)T * D * B;
    size_t stride = (size_t)gridDim.x * blockDim.x;
    for (size_t o = (size_t)blockIdx.x * blockDim.x + threadIdx.x; o < n; o += stride) {
        int b = (int)(o & 63);
        int d = (int)((o >> 6) & 255);
        int t = (int)(o >> 14);
        g_xT[o] = __ldg(x + ((((size_t)b * T + t) << 8) | d));
    }
}

// ---- phase 1: xw0T[t][h][b] = W_ih0[h,:] . x[b][t][:] + (b_ih0+b_hh0)[h] ----
// grid (2048, 4); block 256 = 16 bgrp x 16 hsub; each thread: 8 h-rows x 4 batches
__global__ void __launch_bounds__(256) k_xproj(const float* __restrict__ Wih0,
                                               const float* __restrict__ bih0,
                                               const float* __restrict__ bhh0) {
    extern __shared__ float sm[];
    float* sw = sm;              // [128][256] weight slice (128 KB)
    float* sx = sm + 128 * 256;  // [256][64]  x_t transposed tile (64 KB)
    int t = blockIdx.x, hq = blockIdx.y;
    int tid = threadIdx.x;
    int bgrp = tid & 15, hsub = tid >> 4;

    {   // stage weights (coalesced, linear)
        const float4* s4 = (const float4*)(Wih0 + (size_t)hq * 128 * 256);
        float4* d4 = (float4*)sw;
        #pragma unroll
        for (int r = 0; r < 32; r++) d4[tid + r * 256] = __ldg(s4 + tid + r * 256);
    }
    {   // stage x_t tile (already [d][b] in g_xT — pure linear copy)
        const float4* s4 = (const float4*)(g_xT + (size_t)t * D * B);
        float4* d4 = (float4*)sx;
        #pragma unroll
        for (int r = 0; r < 16; r++) d4[tid + r * 256] = s4[tid + r * 256];
    }
    __syncthreads();

    float4 acc[8];
    #pragma unroll
    for (int j = 0; j < 8; j++) {
        int h = hq * 128 + j * 16 + hsub;
        float bv = __ldg(bih0 + h) + __ldg(bhh0 + h);
        acc[j] = make_float4(bv, bv, bv, bv);
    }
    const float4* sx4 = (const float4*)sx;
    #pragma unroll 4
    for (int k = 0; k < 256; k++) {
        float4 hv = sx4[k * 16 + bgrp];
        #pragma unroll
        for (int j = 0; j < 8; j++) {
            float w = sw[(j * 16 + hsub) * 256 + k];
            acc[j].x = fmaf(w, hv.x, acc[j].x);
            acc[j].y = fmaf(w, hv.y, acc[j].y);
            acc[j].z = fmaf(w, hv.z, acc[j].z);
            acc[j].w = fmaf(w, hv.w, acc[j].w);
        }
    }
    #pragma unroll
    for (int j = 0; j < 8; j++) {
        int h = hq * 128 + j * 16 + hsub;
        *((float4*)(g_xw0T + ((size_t)t * H + h) * B) + bgrp) = acc[j];
    }
}

// ---- phase 2: persistent 3-stage pipelined recurrence, one grid barrier / iter ----
// stage 0 (blocks  0..31): h1[t]   = tanh(xw0[t]      + W_hh0 . h1[t-1]),   t = i
// stage 1 (blocks 32..63): z[t]    =       bias1       + W_ih1 . h1[t],     t = i-1
// stage 2 (blocks 64..95): h2[t]   = tanh(z[t]         + W_hh1 . h2[t-1]),  t = i-2
__global__ void __launch_bounds__(256) k_recur(const float* __restrict__ Whh0,
                                               const float* __restrict__ Wih1,
                                               const float* __restrict__ Whh1,
                                               const float* __restrict__ bih1,
                                               const float* __restrict__ bhh1) {
    extern __shared__ float sm[];
    float* sw = sm;             // [16][512] weight slice (32 KB, loaded once)
    float* sh = sm + 16 * 512;  // [128][64] h staging chunk (32 KB)
    int stage = blockIdx.x >> 5;
    int sub = blockIdx.x & 31;
    int h0 = sub * 16;
    int tid = threadIdx.x;
    int bgrp = tid & 15, hsub = tid >> 4;
    int h = h0 + hsub;

    const float* Wsrc = (stage == 0) ? Whh0 : (stage == 1) ? Wih1 : Whh1;
    {
        const float4* s4 = (const float4*)(Wsrc + (size_t)h0 * 512);
        float4* d4 = (float4*)sw;
        #pragma unroll
        for (int r = 0; r < 8; r++) d4[tid + r * 256] = __ldg(s4 + tid + r * 256);
    }
    float bias = 0.0f;
    if (stage == 1) bias = __ldg(bih1 + h) + __ldg(bhh1 + h);

    unsigned phase = *(volatile unsigned*)&g_bar_phase;  // read before first arrive
    __syncthreads();

    for (int i = 0; i < NITER; i++) {
        bool active = (stage == 0) ? (i < T) : (stage == 1) ? (i >= 1 && i <= T) : (i >= 2);
        if (active) {
            int t = i - stage;
            const float* src = (stage == 0) ? g_h1T[(t - 1) & 1]
                             : (stage == 1) ? g_h1T[t & 1]
                                            : g_h2T[(t - 1) & 1];
            float4 extra;   // issued early, consumed after ~8k cycles -> latency hidden
            if (stage == 0)      extra = __ldcg((const float4*)(g_xw0T + ((size_t)t * H + h) * B) + bgrp);
            else if (stage == 2) extra = __ldcg((const float4*)(g_zT[t & 1] + h * B) + bgrp);
            else                 extra = make_float4(bias, bias, bias, bias);

            float4 acc = make_float4(0.f, 0.f, 0.f, 0.f);
            for (int kc = 0; kc < 4; kc++) {
                const float4* s4 = (const float4*)(src + kc * 128 * B);
                float4* d4 = (float4*)sh;
                #pragma unroll
                for (int r = 0; r < 8; r++) d4[tid + r * 256] = __ldcg(s4 + tid + r * 256);
                __syncthreads();
                const float4* sh4 = (const float4*)sh;
                const float* wrow = sw + hsub * 512 + kc * 128;
                #pragma unroll 4
                for (int kk = 0; kk < 128; kk++) {
                    float w = wrow[kk];
                    float4 hv = sh4[kk * 16 + bgrp];
                    acc.x = fmaf(w, hv.x, acc.x);
                    acc.y = fmaf(w, hv.y, acc.y);
                    acc.z = fmaf(w, hv.z, acc.z);
                    acc.w = fmaf(w, hv.w, acc.w);
                }
                __syncthreads();
            }
            acc.x += extra.x; acc.y += extra.y; acc.z += extra.z; acc.w += extra.w;
            if (stage != 1) {
                acc.x = tanhf(acc.x); acc.y = tanhf(acc.y);
                acc.z = tanhf(acc.z); acc.w = tanhf(acc.w);
            }
            float* dst = (stage == 0) ? g_h1T[t & 1] : (stage == 1) ? g_zT[t & 1] : g_h2T[t & 1];
            __stcg((float4*)(dst + h * B) + bgrp, acc);
        }
        // ---- grid barrier (96 blocks, all resident: 96 < 148 SMs) ----
        __syncthreads();
        if (tid == 0) {
            __threadfence();
            unsigned prev = atomicAdd(&g_bar_count, 1u);
            if (prev == G_BLOCKS - 1) {
                atomicExch(&g_bar_count, 0u);
                __threadfence();
                g_bar_phase = phase + 1;
            } else {
                while (*(volatile unsigned*)&g_bar_phase == phase) {}
            }
            __threadfence();
        }
        __syncthreads();
        phase++;
    }
}

// ---- final FC + softmax on h2[T-1] ----
__global__ void k_fc(const float* __restrict__ fcw, const float* __restrict__ fcb,
                     float* __restrict__ out) {
    __shared__ float logits[64][2];
    int tid = threadIdx.x;  // 128 threads = 64 b x 2 c
    int b = tid >> 1, c = tid & 1;
    const float* h2 = g_h2T[(T - 1) & 1];
    float acc = __ldg(fcb + c);
    for (int k = 0; k < 512; k++)
        acc = fmaf(h2[k * 64 + b], __ldg(fcw + c * 512 + k), acc);
    logits[b][c] = acc;
    __syncthreads();
    if (c == 0) {
        float l0 = logits[b][0], l1 = logits[b][1];
        float m = fmaxf(l0, l1);
        float e0 = expf(l0 - m), e1 = expf(l1 - m);
        float s = e0 + e1;
        out[b * 2 + 0] = e0 / s;
        out[b * 2 + 1] = e1 / s;
    }
}

extern "C" void kernel_launch(void* const* d_in, const int* in_sizes, int n_in,
                              void* d_out, int out_size) {
    const float* x    = (const float*)d_in[0];
    const float* Wih0 = (const float*)d_in[1];
    const float* Whh0 = (const float*)d_in[2];
    const float* bih0 = (const float*)d_in[3];
    const float* bhh0 = (const float*)d_in[4];
    const float* Wih1 = (const float*)d_in[5];
    const float* Whh1 = (const float*)d_in[6];
    const float* bih1 = (const float*)d_in[7];
    const float* bhh1 = (const float*)d_in[8];
    const float* fcw  = (const float*)d_in[9];
    const float* fcb  = (const float*)d_in[10];
    float* out = (float*)d_out;

    cudaFuncSetAttribute(k_xproj, cudaFuncAttributeMaxDynamicSharedMemorySize, 196608);
    cudaFuncSetAttribute(k_recur, cudaFuncAttributeMaxDynamicSharedMemorySize, 65536);

    k_zero<<<256, 256>>>();
    k_transpose<<<4096, 256>>>(x);
    k_xproj<<<dim3(2048, 4), 256, 196608>>>(Wih0, bih0, bhh0);
    k_recur<<<G_BLOCKS, 256, 65536>>>(Whh0, Wih1, Whh1, bih1, bhh1);
    k_fc<<<1, 128>>>(fcw, fcb, out);
}

// round 2
// speedup vs baseline: 1.0850x; 1.0850x over previous
#include <cuda_runtime.h>
#include <math.h>

#define T 2048
#define B 64
#define H 512
#define D 256
#define G_BLOCKS 96
#define NITER (T + 2)

// ---- scratch (static __device__ arrays: no allocation allowed) ----
__device__ float g_xT[(size_t)T * D * B];     // x transposed: [t][d][b]
__device__ float g_xw0T[(size_t)T * H * B];   // layer0 input proj: [t][h][b]
__device__ float g_h1T[2][H * B];             // [parity][h][b]
__device__ float g_h2T[2][H * B];
__device__ float g_zT[2][H * B];              // W_ih1 @ h1 pre-activation
__device__ unsigned g_bar_count;              // zero-initialized
__device__ unsigned g_bar_phase;              // monotonically increasing across replays

// ---- asm helpers ----
__device__ __forceinline__ void lds_v2u64(unsigned addr, unsigned long long& a,
                                          unsigned long long& b) {
    asm volatile("ld.shared.v2.u64 {%0,%1}, [%2];" : "=l"(a), "=l"(b) : "r"(addr));
}
#define FMA2(acc, w, h) \
    asm("fma.rn.f32x2 %0, %1, %2, %0;" : "+l"(acc) : "l"(w), "l"(h))
__device__ __forceinline__ unsigned long long add2(unsigned long long a,
                                                   unsigned long long b) {
    unsigned long long d;
    asm("add.rn.f32x2 %0, %1, %2;" : "=l"(d) : "l"(a), "l"(b));
    return d;
}
__device__ __forceinline__ float2 unpack2(unsigned long long v) {
    float2 r;
    asm("mov.b64 {%0,%1}, %2;" : "=f"(r.x), "=f"(r.y) : "l"(v));
    return r;
}

// ---- zero the recurrent state buffers (must happen every launch) ----
__global__ void k_zero() {
    int idx = blockIdx.x * 256 + threadIdx.x;
    if (idx < 2 * H * B) {
        ((float*)g_h1T)[idx] = 0.0f;
        ((float*)g_h2T)[idx] = 0.0f;
    }
}

// ---- transpose x[b][t][d] -> g_xT[t][d][b] ----
__global__ void k_transpose(const float* __restrict__ x) {
    size_t n = (size_t)T * D * B;
    size_t stride = (size_t)gridDim.x * blockDim.x;
    for (size_t o = (size_t)blockIdx.x * blockDim.x + threadIdx.x; o < n; o += stride) {
        int b = (int)(o & 63);
        int d = (int)((o >> 6) & 255);
        int t = (int)(o >> 14);
        g_xT[o] = __ldg(x + ((((size_t)b * T + t) << 8) | d));
    }
}

// ---- phase 1: xw0T[t][h][b] = W_ih0[h,:] . x[b][t][:] + (b_ih0+b_hh0)[h] ----
__global__ void __launch_bounds__(256) k_xproj(const float* __restrict__ Wih0,
                                               const float* __restrict__ bih0,
                                               const float* __restrict__ bhh0) {
    extern __shared__ float sm[];
    float* sw = sm;              // [128][256] weight slice (128 KB)
    float* sx = sm + 128 * 256;  // [256][64]  x_t tile (64 KB)
    int t = blockIdx.x, hq = blockIdx.y;
    int tid = threadIdx.x;
    int bgrp = tid & 15, hsub = tid >> 4;

    {
        const float4* s4 = (const float4*)(Wih0 + (size_t)hq * 128 * 256);
        float4* d4 = (float4*)sw;
        #pragma unroll
        for (int r = 0; r < 32; r++) d4[tid + r * 256] = __ldg(s4 + tid + r * 256);
    }
    {
        const float4* s4 = (const float4*)(g_xT + (size_t)t * D * B);
        float4* d4 = (float4*)sx;
        #pragma unroll
        for (int r = 0; r < 16; r++) d4[tid + r * 256] = s4[tid + r * 256];
    }
    __syncthreads();

    float4 acc[8];
    #pragma unroll
    for (int j = 0; j < 8; j++) {
        int h = hq * 128 + j * 16 + hsub;
        float bv = __ldg(bih0 + h) + __ldg(bhh0 + h);
        acc[j] = make_float4(bv, bv, bv, bv);
    }
    const float4* sx4 = (const float4*)sx;
    #pragma unroll 4
    for (int k = 0; k < 256; k++) {
        float4 hv = sx4[k * 16 + bgrp];
        #pragma unroll
        for (int j = 0; j < 8; j++) {
            float w = sw[(j * 16 + hsub) * 256 + k];
            acc[j].x = fmaf(w, hv.x, acc[j].x);
            acc[j].y = fmaf(w, hv.y, acc[j].y);
            acc[j].z = fmaf(w, hv.z, acc[j].z);
            acc[j].w = fmaf(w, hv.w, acc[j].w);
        }
    }
    #pragma unroll
    for (int j = 0; j < 8; j++) {
        int h = hq * 128 + j * 16 + hsub;
        *((float4*)(g_xw0T + ((size_t)t * H + h) * B) + bgrp) = acc[j];
    }
}

// ---- phase 2: persistent 3-stage pipelined recurrence ----
// smem: wdup 64KB ([kpair=256][hsub=16] float4 {wk,wk,wk+1,wk+1}) + hbuf 2x32KB
// block = 16 h-rows x 64 batches; thread = 1 row x 4 batches (FFMA2 pairs)
// warp covers ONE batch-half (32 batches) -> 1 crossbar phase per hv LDS
__global__ void __launch_bounds__(256) k_recur(const float* __restrict__ Whh0,
                                               const float* __restrict__ Wih1,
                                               const float* __restrict__ Whh1,
                                               const float* __restrict__ bih1,
                                               const float* __restrict__ bhh1) {
    extern __shared__ float sm[];
    float* wdup = sm;                 // 16384 floats = 64KB
    float* hbuf = sm + 16384;         // 2 slots x 8192 floats = 64KB

    int stage = blockIdx.x >> 5;
    int sub = blockIdx.x & 31;
    int h0 = sub * 16;
    int tid = threadIdx.x;
    int warp = tid >> 5, lane = tid & 31;
    int bhalf = warp & 1;
    int bgrp = lane & 7;
    int hsub = ((warp >> 1) << 2) | (lane >> 3);
    int boff4 = bhalf * 8 + bgrp;     // float4 index within the 16 per k-row
    int h = h0 + hsub;

    // ---- stage weights as duplicated k-pairs: wdup4[kp*16+hsub] = {wk,wk,wk1,wk1}
    const float* Wsrc = (stage == 0) ? Whh0 : (stage == 1) ? Wih1 : Whh1;
    const float* Wr = Wsrc + (size_t)h0 * 512;
    {
        float4* wd4 = (float4*)wdup;
        #pragma unroll
        for (int r = 0; r < 16; r++) {
            int idx = tid + r * 256;          // 0..4095
            int kp = idx >> 4, hs = idx & 15;
            float2 w = __ldg((const float2*)(Wr + (size_t)hs * 512) + kp);
            wd4[idx] = make_float4(w.x, w.x, w.y, w.y);
        }
    }
    float bias = 0.0f;
    if (stage == 1) bias = __ldg(bih1 + h) + __ldg(bhh1 + h);

    unsigned smem_u32 = (unsigned)__cvta_generic_to_shared(sm);
    unsigned wbase = smem_u32 + hsub * 16;
    unsigned hvbase0 = smem_u32 + 65536 + boff4 * 16;  // slot 0

    unsigned phase;
    asm volatile("ld.global.acquire.gpu.u32 %0, [%1];" : "=r"(phase) : "l"(&g_bar_phase) : "memory");
    __syncthreads();

    for (int i = 0; i < NITER; i++) {
        bool active = (stage == 0) ? (i < T) : (stage == 1) ? (i >= 1 && i <= T) : (i >= 2);
        if (active) {
            int t = i - stage;
            const float* src = (stage == 0) ? g_h1T[(t - 1) & 1]
                             : (stage == 1) ? g_h1T[t & 1]
                                            : g_h2T[(t - 1) & 1];
            const float4* src4 = (const float4*)src;

            float4 extra;
            if (stage == 0)      extra = __ldcg((const float4*)(g_xw0T + ((size_t)t * H + h) * B) + boff4);
            else if (stage == 2) extra = __ldcg((const float4*)(g_zT[t & 1] + h * B) + boff4);
            else                 extra = make_float4(bias, bias, bias, bias);

            // prologue: stage chunk 0 into slot 0
            float4 pf[8];
            #pragma unroll
            for (int r = 0; r < 8; r++) pf[r] = __ldcg(src4 + tid + r * 256);
            {
                float4* hd4 = (float4*)hbuf;
                #pragma unroll
                for (int r = 0; r < 8; r++) hd4[tid + r * 256] = pf[r];
            }

            unsigned long long a0 = 0, a1 = 0, b0 = 0, b1 = 0;
            #pragma unroll
            for (int c = 0; c < 4; c++) {
                __syncthreads();   // slot c&1 published
                if (c < 3) {       // prefetch chunk c+1 (latency hidden by compute)
                    #pragma unroll
                    for (int r = 0; r < 8; r++)
                        pf[r] = __ldcg(src4 + (c + 1) * 2048 + tid + r * 256);
                }
                unsigned ha = hvbase0 + (c & 1) * 32768;
                unsigned wa = wbase + c * 16384;   // c*64 kpairs * 256B
                #pragma unroll 8
                for (int kk = 0; kk < 128; kk += 4) {
                    unsigned long long w0, w1, w2, w3;
                    unsigned long long h0a, h0b, h1a, h1b, h2a, h2b, h3a, h3b;
                    lds_v2u64(wa, w0, w1);
                    lds_v2u64(wa + 256, w2, w3);
                    lds_v2u64(ha, h0a, h0b);
                    lds_v2u64(ha + 256, h1a, h1b);
                    lds_v2u64(ha + 512, h2a, h2b);
                    lds_v2u64(ha + 768, h3a, h3b);
                    FMA2(a0, w0, h0a); FMA2(a1, w0, h0b);
                    FMA2(b0, w1, h1a); FMA2(b1, w1, h1b);
                    FMA2(a0, w2, h2a); FMA2(a1, w2, h2b);
                    FMA2(b0, w3, h3a); FMA2(b1, w3, h3b);
                    wa += 512; ha += 1024;
                }
                if (c < 3) {       // store prefetched chunk into the other slot
                    float4* hd4 = (float4*)(hbuf + ((c + 1) & 1) * 8192);
                    #pragma unroll
                    for (int r = 0; r < 8; r++) hd4[tid + r * 256] = pf[r];
                }
            }
            float2 r01 = unpack2(add2(a0, b0));
            float2 r23 = unpack2(add2(a1, b1));
            float4 res;
            res.x = r01.x + extra.x; res.y = r01.y + extra.y;
            res.z = r23.x + extra.z; res.w = r23.y + extra.w;
            if (stage != 1) {
                res.x = tanhf(res.x); res.y = tanhf(res.y);
                res.z = tanhf(res.z); res.w = tanhf(res.w);
            }
            float* dst = (stage == 0) ? g_h1T[t & 1] : (stage == 1) ? g_zT[t & 1] : g_h2T[t & 1];
            __stcg((float4*)(dst + h * B) + boff4, res);
        }
        // ---- release/acquire grid barrier (no MEMBAR.GPU) ----
        __syncthreads();
        if (tid == 0) {
            unsigned prev;
            asm volatile("atom.release.gpu.global.add.u32 %0, [%1], %2;"
                         : "=r"(prev) : "l"(&g_bar_count), "r"(1u) : "memory");
            if (prev == G_BLOCKS - 1) {
                asm volatile("st.relaxed.gpu.global.u32 [%0], %1;"
                             :: "l"(&g_bar_count), "r"(0u) : "memory");
                asm volatile("st.release.gpu.global.u32 [%0], %1;"
                             :: "l"(&g_bar_phase), "r"(phase + 1) : "memory");
            } else {
                unsigned cur;
                do {
                    asm volatile("ld.global.acquire.gpu.u32 %0, [%1];"
                                 : "=r"(cur) : "l"(&g_bar_phase) : "memory");
                } while (cur == phase);
            }
        }
        __syncthreads();
        phase++;
    }
}

// ---- final FC + softmax on h2[T-1] ----
__global__ void k_fc(const float* __restrict__ fcw, const float* __restrict__ fcb,
                     float* __restrict__ out) {
    __shared__ float logits[64][2];
    int tid = threadIdx.x;
    int b = tid >> 1, c = tid & 1;
    const float* h2 = g_h2T[(T - 1) & 1];
    float acc = __ldg(fcb + c);
    for (int k = 0; k < 512; k++)
        acc = fmaf(h2[k * 64 + b], __ldg(fcw + c * 512 + k), acc);
    logits[b][c] = acc;
    __syncthreads();
    if (c == 0) {
        float l0 = logits[b][0], l1 = logits[b][1];
        float m = fmaxf(l0, l1);
        float e0 = expf(l0 - m), e1 = expf(l1 - m);
        float s = e0 + e1;
        out[b * 2 + 0] = e0 / s;
        out[b * 2 + 1] = e1 / s;
    }
}

extern "C" void kernel_launch(void* const* d_in, const int* in_sizes, int n_in,
                              void* d_out, int out_size) {
    const float* x    = (const float*)d_in[0];
    const float* Wih0 = (const float*)d_in[1];
    const float* Whh0 = (const float*)d_in[2];
    const float* bih0 = (const float*)d_in[3];
    const float* bhh0 = (const float*)d_in[4];
    const float* Wih1 = (const float*)d_in[5];
    const float* Whh1 = (const float*)d_in[6];
    const float* bih1 = (const float*)d_in[7];
    const float* bhh1 = (const float*)d_in[8];
    const float* fcw  = (const float*)d_in[9];
    const float* fcb  = (const float*)d_in[10];
    float* out = (float*)d_out;

    cudaFuncSetAttribute(k_xproj, cudaFuncAttributeMaxDynamicSharedMemorySize, 196608);
    cudaFuncSetAttribute(k_recur, cudaFuncAttributeMaxDynamicSharedMemorySize, 131072);

    k_zero<<<256, 256>>>();
    k_transpose<<<4096, 256>>>(x);
    k_xproj<<<dim3(2048, 4), 256, 196608>>>(Wih0, bih0, bhh0);
    k_recur<<<G_BLOCKS, 256, 131072>>>(Whh0, Wih1, Whh1, bih1, bhh1);
    k_fc<<<1, 128>>>(fcw, fcb, out);
}